// round 1
// baseline (speedup 1.0000x reference)
#include <cuda_runtime.h>
#include <math.h>

#define BATCH 128
#define NTOK  196
#define DIMC  384
#define KBASE 16
#define NH    6
#define HD    64
#define DR    96

// mix buffer padded to 8 per (n,k) so (k-slice) loads are 16B-aligned
__device__ float g_mix[BATCH * NTOK * KBASE * 8];

__device__ __forceinline__ float gelu_exact(float v) {
    return 0.5f * v * (1.0f + erff(v * 0.70710678118654752440f));
}

// ---------------------------------------------------------------------------
// Kernel 1: mix[b,n,k,h] = softmax_k( (gelu(x@W1+b1) @ W2 + b2) )
// One CTA = 32 rows of (b,n), 96 threads (one per output column j).
// x and hid are staged TRANSPOSED in smem so the per-column dot products read
// 32 row-values with vectorized broadcast LDS.128.
// ---------------------------------------------------------------------------
#define K1_ROWS 32
#define XTS 36   // padded row stride (conflict mitigation + 16B alignment)
#define K1_SMEM ((DIMC*XTS + DR*XTS + K1_ROWS*DR) * 4)

__global__ void __launch_bounds__(96) k1_mlp(
    const float* __restrict__ x,
    const float* __restrict__ W1, const float* __restrict__ b1,
    const float* __restrict__ W2, const float* __restrict__ b2)
{
    extern __shared__ float sm1[];
    float* xs_t  = sm1;                      // [384][XTS] transposed x rows
    float* hid_t = sm1 + DIMC*XTS;           // [96][XTS]  transposed hid
    float* l_s   = sm1 + DIMC*XTS + DR*XTS;  // [32][96]   logits / exp

    const int tid  = threadIdx.x;
    const int row0 = blockIdx.x * K1_ROWS;

    // ---- transpose-load x: lane = row (conflict-free STS), warp = d4 group
    {
        int r  = tid & 31;
        int d0 = tid >> 5;   // 0..2
        const float4* X4 = (const float4*)x;
        for (int d4 = d0; d4 < 96; d4 += 3) {
            float4 v = X4[(size_t)(row0 + r) * 96 + d4];
            int dd = d4 * 4;
            xs_t[(dd+0)*XTS + r] = v.x;
            xs_t[(dd+1)*XTS + r] = v.y;
            xs_t[(dd+2)*XTS + r] = v.z;
            xs_t[(dd+3)*XTS + r] = v.w;
        }
    }
    __syncthreads();

    const int j = tid;   // output column 0..95
    float acc[K1_ROWS];

    // ---- hid = gelu(x @ W1 + b1), column j for 32 rows
    {
        float bv = __ldg(&b1[j]);
        #pragma unroll
        for (int r = 0; r < K1_ROWS; r++) acc[r] = bv;
    }
    #pragma unroll 4
    for (int i = 0; i < DIMC; i++) {
        float w = __ldg(&W1[i*DR + j]);
        const float4* xr = (const float4*)(xs_t + i*XTS);
        #pragma unroll
        for (int r4 = 0; r4 < 8; r4++) {
            float4 xv = xr[r4];
            acc[r4*4+0] += w*xv.x;
            acc[r4*4+1] += w*xv.y;
            acc[r4*4+2] += w*xv.z;
            acc[r4*4+3] += w*xv.w;
        }
    }
    // gelu + store transposed (vector STS)
    {
        float4* hrow = (float4*)(hid_t + j*XTS);
        #pragma unroll
        for (int r4 = 0; r4 < 8; r4++) {
            float4 g;
            g.x = gelu_exact(acc[r4*4+0]);
            g.y = gelu_exact(acc[r4*4+1]);
            g.z = gelu_exact(acc[r4*4+2]);
            g.w = gelu_exact(acc[r4*4+3]);
            hrow[r4] = g;
        }
    }
    __syncthreads();

    // ---- logits = hid @ W2 + b2
    {
        float bv = __ldg(&b2[j]);
        #pragma unroll
        for (int r = 0; r < K1_ROWS; r++) acc[r] = bv;
    }
    #pragma unroll 4
    for (int i = 0; i < DR; i++) {
        float w = __ldg(&W2[i*DR + j]);
        const float4* hr = (const float4*)(hid_t + i*XTS);
        #pragma unroll
        for (int r4 = 0; r4 < 8; r4++) {
            float4 hv = hr[r4];
            acc[r4*4+0] += w*hv.x;
            acc[r4*4+1] += w*hv.y;
            acc[r4*4+2] += w*hv.z;
            acc[r4*4+3] += w*hv.w;
        }
    }
    #pragma unroll
    for (int r = 0; r < K1_ROWS; r++) l_s[r*DR + j] = acc[r];
    __syncthreads();

    // ---- softmax over k (column j = k*6+h)
    const int kk = j / NH;
    const int hh = j - kk * NH;
    float mx[K1_ROWS];
    #pragma unroll 4
    for (int r = 0; r < K1_ROWS; r++) {
        float m = -1e30f;
        #pragma unroll
        for (int q = 0; q < KBASE; q++)
            m = fmaxf(m, l_s[r*DR + q*NH + hh]);
        mx[r] = m;
    }
    __syncthreads();
    #pragma unroll 4
    for (int r = 0; r < K1_ROWS; r++) {
        float e = expf(acc[r] - mx[r]);
        acc[r] = e;
        l_s[r*DR + j] = e;
    }
    __syncthreads();
    #pragma unroll 2
    for (int r = 0; r < K1_ROWS; r++) {
        float s = 0.0f;
        #pragma unroll
        for (int q = 0; q < KBASE; q++)
            s += l_s[r*DR + q*NH + hh];
        g_mix[(size_t)(row0 + r)*(KBASE*8) + kk*8 + hh] = acc[r] / s;
    }
}

// ---------------------------------------------------------------------------
// Kernel 2: per (b, m_tile):
//   Phase A: A[h, m_local, n] = sum_k mix[b,n,k,h] * wb[k,n,m]   (SMEM)
//   Phase B: out[b, m, h*64+c] = sum_n A[h,m,n] * x[b,n,h*64+c]
// m_tile = 28 (196 = 7*28). Phase B register tile = 7m x 8c per thread,
// thread map (h=tid>>5, mg=(tid>>3)&3, cg=tid&7), 192 threads.
// ---------------------------------------------------------------------------
#define MT  28
#define NMT 7
#define CHN 56
#define K2_SMEM ((NH*MT*NTOK + CHN*DIMC) * 4)

__global__ void __launch_bounds__(192) k2_mix(
    const float* __restrict__ x,
    const float* __restrict__ wb,
    float* __restrict__ out)
{
    extern __shared__ float sm2[];
    float* As = sm2;                 // [6][28][196]
    float* Xs = sm2 + NH*MT*NTOK;    // [56][384]

    const int tid = threadIdx.x;
    const int mt  = blockIdx.x;
    const int b   = blockIdx.y;

    // ---------------- Phase A ----------------
    if (tid < 189) {
        const int m4 = tid % 7;       // which group of 4 m-columns
        const int nl = tid / 7;       // 0..26 n-lane
        const int m0 = mt*MT + m4*4;  // global m base
        for (int n = nl; n < NTOK; n += 27) {
            float a[NH][4];
            #pragma unroll
            for (int h = 0; h < NH; h++)
                #pragma unroll
                for (int q = 0; q < 4; q++) a[h][q] = 0.0f;

            const float* mixp = g_mix + (size_t)(b*NTOK + n)*(KBASE*8);
            const float* wbp  = wb + (size_t)n*NTOK + m0;
            #pragma unroll 4
            for (int k = 0; k < KBASE; k++) {
                float4 w   = *(const float4*)(wbp + (size_t)k*NTOK*NTOK);
                float4 m03 = *(const float4*)(mixp + k*8);
                float2 m45 = *(const float2*)(mixp + k*8 + 4);
                a[0][0]+=m03.x*w.x; a[0][1]+=m03.x*w.y; a[0][2]+=m03.x*w.z; a[0][3]+=m03.x*w.w;
                a[1][0]+=m03.y*w.x; a[1][1]+=m03.y*w.y; a[1][2]+=m03.y*w.z; a[1][3]+=m03.y*w.w;
                a[2][0]+=m03.z*w.x; a[2][1]+=m03.z*w.y; a[2][2]+=m03.z*w.z; a[2][3]+=m03.z*w.w;
                a[3][0]+=m03.w*w.x; a[3][1]+=m03.w*w.y; a[3][2]+=m03.w*w.z; a[3][3]+=m03.w*w.w;
                a[4][0]+=m45.x*w.x; a[4][1]+=m45.x*w.y; a[4][2]+=m45.x*w.z; a[4][3]+=m45.x*w.w;
                a[5][0]+=m45.y*w.x; a[5][1]+=m45.y*w.y; a[5][2]+=m45.y*w.z; a[5][3]+=m45.y*w.w;
            }
            #pragma unroll
            for (int h = 0; h < NH; h++) {
                #pragma unroll
                for (int q = 0; q < 4; q++)
                    As[(h*MT + m4*4 + q)*NTOK + n] = a[h][q];
            }
        }
    }
    __syncthreads();

    // ---------------- Phase B ----------------
    const int cg = tid & 7;
    const int mg = (tid >> 3) & 3;
    const int h  = tid >> 5;   // 0..5

    float acc[7][8];
    #pragma unroll
    for (int i = 0; i < 7; i++)
        #pragma unroll
        for (int q = 0; q < 8; q++) acc[i][q] = 0.0f;

    const float4* Xg4 = (const float4*)(x + (size_t)b*NTOK*DIMC);
    const float*  Arow = As + (h*MT + mg*7)*NTOK;
    const float*  xbase = Xs + h*HD + cg*8;

    for (int n0 = 0; n0 < NTOK; n0 += CHN) {
        int ch = NTOK - n0; if (ch > CHN) ch = CHN;
        // stage x chunk (rows are contiguous -> flat float4 copy)
        for (int f = tid; f < ch*96; f += 192)
            ((float4*)Xs)[f] = Xg4[(size_t)n0*96 + f];
        __syncthreads();

        for (int n4 = 0; n4 < ch; n4 += 4) {
            float4 a4[7];
            #pragma unroll
            for (int i = 0; i < 7; i++)
                a4[i] = *(const float4*)(Arow + i*NTOK + n0 + n4);

#define DO_J(CMP, OFF) { \
    const float* xp = xbase + (size_t)(n4+(OFF))*DIMC; \
    float4 xa = *(const float4*)xp; \
    float4 xb2 = *(const float4*)(xp+4); \
    _Pragma("unroll") \
    for (int i = 0; i < 7; i++) { float av = a4[i].CMP; \
        acc[i][0]+=av*xa.x;  acc[i][1]+=av*xa.y;  acc[i][2]+=av*xa.z;  acc[i][3]+=av*xa.w; \
        acc[i][4]+=av*xb2.x; acc[i][5]+=av*xb2.y; acc[i][6]+=av*xb2.z; acc[i][7]+=av*xb2.w; } }
            DO_J(x,0)
            DO_J(y,1)
            DO_J(z,2)
            DO_J(w,3)
#undef DO_J
        }
        __syncthreads();
    }

    // ---------------- write out ----------------
    float* ob = out + ((size_t)b*NTOK + (size_t)mt*MT + mg*7)*DIMC + h*HD + cg*8;
    #pragma unroll
    for (int i = 0; i < 7; i++) {
        *(float4*)(ob + (size_t)i*DIMC)     = make_float4(acc[i][0], acc[i][1], acc[i][2], acc[i][3]);
        *(float4*)(ob + (size_t)i*DIMC + 4) = make_float4(acc[i][4], acc[i][5], acc[i][6], acc[i][7]);
    }
}

// ---------------------------------------------------------------------------
extern "C" void kernel_launch(void* const* d_in, const int* in_sizes, int n_in,
                              void* d_out, int out_size)
{
    const float* x  = (const float*)d_in[0];
    const float* W1 = (const float*)d_in[1];
    const float* b1 = (const float*)d_in[2];
    const float* W2 = (const float*)d_in[3];
    const float* b2 = (const float*)d_in[4];
    const float* wb = (const float*)d_in[5];
    float* out = (float*)d_out;

    cudaFuncSetAttribute((const void*)k1_mlp,
                         cudaFuncAttributeMaxDynamicSharedMemorySize, K1_SMEM);
    cudaFuncSetAttribute((const void*)k2_mix,
                         cudaFuncAttributeMaxDynamicSharedMemorySize, K2_SMEM);

    k1_mlp<<<(BATCH*NTOK)/K1_ROWS, 96, K1_SMEM>>>(x, W1, b1, W2, b2);
    dim3 g2(NMT, BATCH);
    k2_mix<<<g2, 192, K2_SMEM>>>(x, wb, out);
}

// round 2
// speedup vs baseline: 1.0376x; 1.0376x over previous
#include <cuda_runtime.h>
#include <math.h>

#define BATCH 128
#define NTOK  196
#define DIMC  384
#define KBASE 16
#define NH    6
#define HD    64
#define DR    96

typedef unsigned long long ull;

// mix stored DUPLICATED: per (b,n): 16 k * 6 h * 2 copies = 192 floats = 96 ull
__device__ ull g_mix2[(size_t)BATCH * NTOK * 96];

__device__ __forceinline__ void fma2(ull &d, ull a, ull b) {
    asm("fma.rn.f32x2 %0, %1, %2, %0;" : "+l"(d) : "l"(a), "l"(b));
}
__device__ __forceinline__ ull dup2(float v) {
    ull r; asm("mov.b64 %0, {%1, %1};" : "=l"(r) : "f"(v)); return r;
}
__device__ __forceinline__ void unpack2(ull v, float &lo, float &hi) {
    asm("mov.b64 {%0, %1}, %2;" : "=f"(lo), "=f"(hi) : "l"(v));
}
__device__ __forceinline__ float gelu_exact(float v) {
    return 0.5f * v * (1.0f + erff(v * 0.70710678118654752440f));
}

// ---------------------------------------------------------------------------
// Kernel 1: mix[b,n,k,h] = softmax_k( gelu(x@W1+b1) @ W2 + b2 ), duplicated out
// CTA: 64 rows, 256 threads. Register tile 8r x 3c, packed over r (f32x2).
// smem: xs_t [96][68] (i-chunk transposed), ws [96][96], hid_t [96][72]
// ---------------------------------------------------------------------------
#define K1_ROWS 64
#define XTP 68
#define HTP 72
#define K1_SMEM ((96*XTP + 96*96 + 96*HTP) * 4)

__global__ void __launch_bounds__(256) k1_mlp(
    const float* __restrict__ x,
    const float* __restrict__ W1, const float* __restrict__ b1,
    const float* __restrict__ W2, const float* __restrict__ b2)
{
    extern __shared__ float sm1[];
    float* xs_t  = sm1;                    // [96][XTP]  (reused later as logits [64][96])
    float* ws    = sm1 + 96*XTP;           // [96][96]
    float* hid_t = sm1 + 96*XTP + 96*96;   // [96][HTP]
    float* lg    = xs_t;

    const int tid  = threadIdx.x;
    const int row0 = blockIdx.x * K1_ROWS;
    const int rg   = tid & 7;     // 8 row-groups of 8 rows
    const int cg   = tid >> 3;    // 32 col-groups of 3 cols

    const float4* X4  = (const float4*)x;
    const float4* W14 = (const float4*)W1;
    const float4* W24 = (const float4*)W2;

    // ---- GEMM1: hid = gelu(x @ W1 + b1) over 4 chunks of 96 i
    ull acc[4][3];
    {
        #pragma unroll
        for (int cc = 0; cc < 3; cc++) {
            ull bv = dup2(__ldg(&b1[cg*3 + cc]));
            #pragma unroll
            for (int rp = 0; rp < 4; rp++) acc[rp][cc] = bv;
        }
    }

    for (int ci = 0; ci < 4; ci++) {
        __syncthreads();
        // stage x chunk transposed: xs_t[i][r]
        for (int f = tid; f < 1536; f += 256) {
            int r = f / 24, iv = f % 24;
            float4 v = X4[(size_t)(row0 + r) * 96 + ci*24 + iv];
            xs_t[(iv*4+0)*XTP + r] = v.x;
            xs_t[(iv*4+1)*XTP + r] = v.y;
            xs_t[(iv*4+2)*XTP + r] = v.z;
            xs_t[(iv*4+3)*XTP + r] = v.w;
        }
        // stage W1 chunk (flat copy)
        for (int f = tid; f < 2304; f += 256)
            ((float4*)ws)[f] = W14[ci*2304 + f];
        __syncthreads();

        #pragma unroll 4
        for (int i = 0; i < 96; i++) {
            ulonglong2 xa = *(const ulonglong2*)(xs_t + i*XTP + rg*8);
            ulonglong2 xb = *(const ulonglong2*)(xs_t + i*XTP + rg*8 + 4);
            const float* wr = ws + i*96 + cg*3;
            ull w0 = dup2(wr[0]), w1 = dup2(wr[1]), w2 = dup2(wr[2]);
            fma2(acc[0][0], xa.x, w0); fma2(acc[0][1], xa.x, w1); fma2(acc[0][2], xa.x, w2);
            fma2(acc[1][0], xa.y, w0); fma2(acc[1][1], xa.y, w1); fma2(acc[1][2], xa.y, w2);
            fma2(acc[2][0], xb.x, w0); fma2(acc[2][1], xb.x, w1); fma2(acc[2][2], xb.x, w2);
            fma2(acc[3][0], xb.y, w0); fma2(acc[3][1], xb.y, w1); fma2(acc[3][2], xb.y, w2);
        }
    }
    __syncthreads();

    // ---- GELU + store hid transposed: hid_t[c][r]
    #pragma unroll
    for (int cc = 0; cc < 3; cc++) {
        float* hrow = hid_t + (cg*3 + cc)*HTP + rg*8;
        #pragma unroll
        for (int rp = 0; rp < 4; rp++) {
            float lo, hi; unpack2(acc[rp][cc], lo, hi);
            hrow[2*rp]   = gelu_exact(lo);
            hrow[2*rp+1] = gelu_exact(hi);
        }
    }
    // stage W2 (flat copy)
    for (int f = tid; f < 2304; f += 256)
        ((float4*)ws)[f] = W24[f];
    __syncthreads();

    // ---- GEMM2: logits = hid @ W2 + b2
    {
        #pragma unroll
        for (int cc = 0; cc < 3; cc++) {
            ull bv = dup2(__ldg(&b2[cg*3 + cc]));
            #pragma unroll
            for (int rp = 0; rp < 4; rp++) acc[rp][cc] = bv;
        }
    }
    #pragma unroll 4
    for (int i = 0; i < 96; i++) {
        ulonglong2 xa = *(const ulonglong2*)(hid_t + i*HTP + rg*8);
        ulonglong2 xb = *(const ulonglong2*)(hid_t + i*HTP + rg*8 + 4);
        const float* wr = ws + i*96 + cg*3;
        ull w0 = dup2(wr[0]), w1 = dup2(wr[1]), w2 = dup2(wr[2]);
        fma2(acc[0][0], xa.x, w0); fma2(acc[0][1], xa.x, w1); fma2(acc[0][2], xa.x, w2);
        fma2(acc[1][0], xa.y, w0); fma2(acc[1][1], xa.y, w1); fma2(acc[1][2], xa.y, w2);
        fma2(acc[2][0], xb.x, w0); fma2(acc[2][1], xb.x, w1); fma2(acc[2][2], xb.x, w2);
        fma2(acc[3][0], xb.y, w0); fma2(acc[3][1], xb.y, w1); fma2(acc[3][2], xb.y, w2);
    }
    // store logits [r][96] into lg (= xs_t region, no longer needed)
    #pragma unroll
    for (int cc = 0; cc < 3; cc++) {
        #pragma unroll
        for (int rp = 0; rp < 4; rp++) {
            float lo, hi; unpack2(acc[rp][cc], lo, hi);
            lg[(rg*8 + 2*rp)*96   + cg*3 + cc] = lo;
            lg[(rg*8 + 2*rp+1)*96 + cg*3 + cc] = hi;
        }
    }
    __syncthreads();

    // ---- softmax over k per (row, h); write duplicated mix
    if (tid < 192) {
        const int h  = tid % NH;
        const int rp = tid / NH;   // 0..31 -> rows 2rp, 2rp+1
        #pragma unroll
        for (int q = 0; q < 2; q++) {
            int r = 2*rp + q;
            const float* lrow = lg + r*96 + h;
            float e[KBASE];
            float m = -1e30f;
            #pragma unroll
            for (int k = 0; k < KBASE; k++) { e[k] = lrow[k*6]; m = fmaxf(m, e[k]); }
            float s = 0.0f;
            #pragma unroll
            for (int k = 0; k < KBASE; k++) { e[k] = __expf(e[k] - m); s += e[k]; }
            float inv = 1.0f / s;
            ull* gm = g_mix2 + (size_t)(row0 + r)*96 + h;
            #pragma unroll
            for (int k = 0; k < KBASE; k++)
                gm[k*6] = dup2(e[k] * inv);
        }
    }
}

// ---------------------------------------------------------------------------
// Kernel 2: per (mt, hs, b) CTA (3 heads per CTA):
//   Phase A: As[hl][n][m] = sum_k mix[b,n,k,h] * wb[k,n,m]    m-contiguous
//   Phase B: out[b,m,h*64+c] = sum_n As[hl][m? ..] -- reg tile 14 m-pairs
// 192 threads, smem ~104KB -> 2 CTAs/SM.
// ---------------------------------------------------------------------------
#define MT   28
#define NMT  7
#define CHN  49
#define K2_SMEM ((3*NTOK*MT + CHN*192) * 4)

__global__ void __launch_bounds__(192) k2_mix(
    const float* __restrict__ x,
    const float* __restrict__ wb,
    float* __restrict__ out)
{
    extern __shared__ float sm2[];
    float* As = sm2;                  // [3][196][28]
    float* Xs = sm2 + 3*NTOK*MT;      // [CHN][192]

    const int tid = threadIdx.x;
    const int mt  = blockIdx.x;
    const int hs  = blockIdx.y;       // 0 or 1 (heads hs*3 .. hs*3+2)
    const int b   = blockIdx.z;

    // ---------------- Phase A ----------------
    if (tid < 189) {
        const int m4 = tid % 7;
        const int nl = tid / 7;            // 0..26
        const int m0 = mt*MT + m4*4;
        for (int n = nl; n < NTOK; n += 27) {
            ull a[3][2];
            #pragma unroll
            for (int hl = 0; hl < 3; hl++) { a[hl][0] = 0ULL; a[hl][1] = 0ULL; }
            const ull*   gmrow = g_mix2 + (size_t)(b*NTOK + n)*96 + hs*3;
            const float* wrow  = wb + (size_t)n*NTOK + m0;
            #pragma unroll 4
            for (int k = 0; k < KBASE; k++) {
                ulonglong2 w2v = *(const ulonglong2*)(wrow + (size_t)k*(NTOK*NTOK));
                ull d0 = gmrow[k*6], d1 = gmrow[k*6+1], d2 = gmrow[k*6+2];
                fma2(a[0][0], d0, w2v.x); fma2(a[0][1], d0, w2v.y);
                fma2(a[1][0], d1, w2v.x); fma2(a[1][1], d1, w2v.y);
                fma2(a[2][0], d2, w2v.x); fma2(a[2][1], d2, w2v.y);
            }
            #pragma unroll
            for (int hl = 0; hl < 3; hl++) {
                ulonglong2 st; st.x = a[hl][0]; st.y = a[hl][1];
                *(ulonglong2*)(As + (hl*NTOK + n)*MT + m4*4) = st;
            }
        }
    }

    // ---------------- Phase B ----------------
    const int hl = tid >> 6;          // 0..2
    // channel within Xs slab == tid (hl*64 + c)
    ull acc[14];
    #pragma unroll
    for (int j = 0; j < 14; j++) acc[j] = 0ULL;

    const float4* Xg4 = (const float4*)(x + (size_t)b*NTOK*DIMC);

    for (int n0 = 0; n0 < NTOK; n0 += CHN) {
        // stage x chunk: this CTA's 192 channels only
        for (int f = tid; f < CHN*48; f += 192) {
            int nn = f / 48, cv = f % 48;
            ((float4*)Xs)[f] = Xg4[(size_t)(n0+nn)*96 + hs*48 + cv];
        }
        __syncthreads();

        const ulonglong2* ap = (const ulonglong2*)(As + (hl*NTOK + n0)*MT);
        const float* xrow = Xs + tid;
        #pragma unroll 2
        for (int nn = 0; nn < CHN; nn++) {
            ull xd = dup2(xrow[nn*192]);
            ulonglong2 q0 = ap[0], q1 = ap[1], q2 = ap[2], q3 = ap[3],
                       q4 = ap[4], q5 = ap[5], q6 = ap[6];
            ap += 7;
            fma2(acc[0],  q0.x, xd); fma2(acc[1],  q0.y, xd);
            fma2(acc[2],  q1.x, xd); fma2(acc[3],  q1.y, xd);
            fma2(acc[4],  q2.x, xd); fma2(acc[5],  q2.y, xd);
            fma2(acc[6],  q3.x, xd); fma2(acc[7],  q3.y, xd);
            fma2(acc[8],  q4.x, xd); fma2(acc[9],  q4.y, xd);
            fma2(acc[10], q5.x, xd); fma2(acc[11], q5.y, xd);
            fma2(acc[12], q6.x, xd); fma2(acc[13], q6.y, xd);
        }
        __syncthreads();
    }

    // ---------------- write out ----------------
    float* ob = out + ((size_t)(b*NTOK + mt*MT))*DIMC + hs*192 + tid;
    #pragma unroll
    for (int j = 0; j < 14; j++) {
        float lo, hi; unpack2(acc[j], lo, hi);
        ob[(2*j)*DIMC]   = lo;
        ob[(2*j+1)*DIMC] = hi;
    }
}

// ---------------------------------------------------------------------------
extern "C" void kernel_launch(void* const* d_in, const int* in_sizes, int n_in,
                              void* d_out, int out_size)
{
    const float* x  = (const float*)d_in[0];
    const float* W1 = (const float*)d_in[1];
    const float* b1 = (const float*)d_in[2];
    const float* W2 = (const float*)d_in[3];
    const float* b2 = (const float*)d_in[4];
    const float* wb = (const float*)d_in[5];
    float* out = (float*)d_out;

    cudaFuncSetAttribute((const void*)k1_mlp,
                         cudaFuncAttributeMaxDynamicSharedMemorySize, K1_SMEM);
    cudaFuncSetAttribute((const void*)k2_mix,
                         cudaFuncAttributeMaxDynamicSharedMemorySize, K2_SMEM);

    k1_mlp<<<(BATCH*NTOK)/K1_ROWS, 256, K1_SMEM>>>(x, W1, b1, W2, b2);
    dim3 g2(NMT, 2, BATCH);
    k2_mix<<<g2, 192, K2_SMEM>>>(x, wb, out);
}

// round 4
// speedup vs baseline: 1.5350x; 1.4794x over previous
#include <cuda_runtime.h>
#include <stdint.h>
#include <math.h>

#define BATCH 128
#define NTOK  196
#define DIMC  384
#define KBASE 16
#define NH    6
#define HD    64
#define DR    96

typedef unsigned long long ull;

// mix stored DUPLICATED: per (b,n): 16 k * 6 h * 2 copies = 192 floats = 96 ull
__device__ __align__(16) ull g_mix2[(size_t)BATCH * NTOK * 96];

__device__ __forceinline__ void fma2(ull &d, ull a, ull b) {
    asm("fma.rn.f32x2 %0, %1, %2, %0;" : "+l"(d) : "l"(a), "l"(b));
}
__device__ __forceinline__ ull dup2(float v) {
    ull r; asm("mov.b64 %0, {%1, %1};" : "=l"(r) : "f"(v)); return r;
}
__device__ __forceinline__ void unpack2(ull v, float &lo, float &hi) {
    asm("mov.b64 {%0, %1}, %2;" : "=f"(lo), "=f"(hi) : "l"(v));
}
__device__ __forceinline__ float gelu_exact(float v) {
    return 0.5f * v * (1.0f + erff(v * 0.70710678118654752440f));
}
__device__ __forceinline__ void cp16(void* dst_smem, const void* src) {
    unsigned int d = (unsigned int)__cvta_generic_to_shared(dst_smem);
    asm volatile("cp.async.cg.shared.global [%0], [%1], 16;" :: "r"(d), "l"(src));
}
__device__ __forceinline__ void cp_commit() {
    asm volatile("cp.async.commit_group;" ::: "memory");
}

// ---------------------------------------------------------------------------
// Kernel 1: mix[b,n,k,h] = softmax_k( gelu(x@W1+b1) @ W2 + b2 ), duplicated out
// CTA: 64 rows, 192 threads. Register tile 8r x 4c packed over r (f32x2).
// ---------------------------------------------------------------------------
#define K1_ROWS 64
#define XTP 68
#define HTP 72
#define K1_SMEM ((96*XTP + 96*96 + 96*HTP) * 4)

__global__ void __launch_bounds__(192) k1_mlp(
    const float* __restrict__ x,
    const float* __restrict__ W1, const float* __restrict__ b1,
    const float* __restrict__ W2, const float* __restrict__ b2)
{
    extern __shared__ float sm1[];
    float* xs_t  = sm1;                    // [96][XTP] chunk transposed (later logits)
    float* ws    = sm1 + 96*XTP;           // [96][96]
    float* hid_t = sm1 + 96*XTP + 96*96;   // [96][HTP]
    float* lg    = xs_t;

    const int tid  = threadIdx.x;
    const int row0 = blockIdx.x * K1_ROWS;
    const int rg   = tid & 7;     // 8 row-groups of 8 rows
    const int cg   = tid >> 3;    // 24 col-groups of 4 cols

    const float4* X4  = (const float4*)x;
    const float4* W14 = (const float4*)W1;
    const float4* W24 = (const float4*)W2;

    ull acc[4][4];
    {
        float4 bv4 = *(const float4*)(b1 + cg*4);
        #pragma unroll
        for (int rp = 0; rp < 4; rp++) {
            acc[rp][0] = dup2(bv4.x); acc[rp][1] = dup2(bv4.y);
            acc[rp][2] = dup2(bv4.z); acc[rp][3] = dup2(bv4.w);
        }
    }

    // ---- GEMM1: hid = gelu(x @ W1 + b1) over 4 chunks of 96 i
    for (int ci = 0; ci < 4; ci++) {
        __syncthreads();
        // stage x chunk transposed: xs_t[i][r]
        for (int f = tid; f < 1536; f += 192) {
            int r = f / 24, iv = f % 24;
            float4 v = X4[(size_t)(row0 + r) * 96 + ci*24 + iv];
            xs_t[(iv*4+0)*XTP + r] = v.x;
            xs_t[(iv*4+1)*XTP + r] = v.y;
            xs_t[(iv*4+2)*XTP + r] = v.z;
            xs_t[(iv*4+3)*XTP + r] = v.w;
        }
        for (int f = tid; f < 2304; f += 192)
            ((float4*)ws)[f] = W14[ci*2304 + f];
        __syncthreads();

        #pragma unroll 8
        for (int i = 0; i < 96; i++) {
            ulonglong2 xa = *(const ulonglong2*)(xs_t + i*XTP + rg*8);
            ulonglong2 xb = *(const ulonglong2*)(xs_t + i*XTP + rg*8 + 4);
            float4 wv = *(const float4*)(ws + i*96 + cg*4);
            ull w0 = dup2(wv.x), w1 = dup2(wv.y), w2 = dup2(wv.z), w3 = dup2(wv.w);
            fma2(acc[0][0], xa.x, w0); fma2(acc[0][1], xa.x, w1);
            fma2(acc[0][2], xa.x, w2); fma2(acc[0][3], xa.x, w3);
            fma2(acc[1][0], xa.y, w0); fma2(acc[1][1], xa.y, w1);
            fma2(acc[1][2], xa.y, w2); fma2(acc[1][3], xa.y, w3);
            fma2(acc[2][0], xb.x, w0); fma2(acc[2][1], xb.x, w1);
            fma2(acc[2][2], xb.x, w2); fma2(acc[2][3], xb.x, w3);
            fma2(acc[3][0], xb.y, w0); fma2(acc[3][1], xb.y, w1);
            fma2(acc[3][2], xb.y, w2); fma2(acc[3][3], xb.y, w3);
        }
    }
    __syncthreads();

    // ---- GELU + store hid transposed: hid_t[c][r]
    #pragma unroll
    for (int cc = 0; cc < 4; cc++) {
        float2* hrow = (float2*)(hid_t + (cg*4 + cc)*HTP + rg*8);
        #pragma unroll
        for (int rp = 0; rp < 4; rp++) {
            float lo, hi; unpack2(acc[rp][cc], lo, hi);
            hrow[rp] = make_float2(gelu_exact(lo), gelu_exact(hi));
        }
    }
    for (int f = tid; f < 2304; f += 192)
        ((float4*)ws)[f] = W24[f];
    __syncthreads();

    // ---- GEMM2: logits = hid @ W2 + b2
    {
        float4 bv4 = *(const float4*)(b2 + cg*4);
        #pragma unroll
        for (int rp = 0; rp < 4; rp++) {
            acc[rp][0] = dup2(bv4.x); acc[rp][1] = dup2(bv4.y);
            acc[rp][2] = dup2(bv4.z); acc[rp][3] = dup2(bv4.w);
        }
    }
    #pragma unroll 8
    for (int i = 0; i < 96; i++) {
        ulonglong2 xa = *(const ulonglong2*)(hid_t + i*HTP + rg*8);
        ulonglong2 xb = *(const ulonglong2*)(hid_t + i*HTP + rg*8 + 4);
        float4 wv = *(const float4*)(ws + i*96 + cg*4);
        ull w0 = dup2(wv.x), w1 = dup2(wv.y), w2 = dup2(wv.z), w3 = dup2(wv.w);
        fma2(acc[0][0], xa.x, w0); fma2(acc[0][1], xa.x, w1);
        fma2(acc[0][2], xa.x, w2); fma2(acc[0][3], xa.x, w3);
        fma2(acc[1][0], xa.y, w0); fma2(acc[1][1], xa.y, w1);
        fma2(acc[1][2], xa.y, w2); fma2(acc[1][3], xa.y, w3);
        fma2(acc[2][0], xb.x, w0); fma2(acc[2][1], xb.x, w1);
        fma2(acc[2][2], xb.x, w2); fma2(acc[2][3], xb.x, w3);
        fma2(acc[3][0], xb.y, w0); fma2(acc[3][1], xb.y, w1);
        fma2(acc[3][2], xb.y, w2); fma2(acc[3][3], xb.y, w3);
    }
    __syncthreads();
    // store logits [r][96]
    #pragma unroll
    for (int cc = 0; cc < 4; cc++) {
        #pragma unroll
        for (int rp = 0; rp < 4; rp++) {
            float lo, hi; unpack2(acc[rp][cc], lo, hi);
            lg[(rg*8 + 2*rp)*96   + cg*4 + cc] = lo;
            lg[(rg*8 + 2*rp+1)*96 + cg*4 + cc] = hi;
        }
    }
    __syncthreads();

    // ---- softmax over k per (row, h); write duplicated mix
    {
        const int h  = tid % NH;
        const int rp = tid / NH;   // 0..31
        #pragma unroll
        for (int q = 0; q < 2; q++) {
            int r = 2*rp + q;
            const float* lrow = lg + r*96 + h;
            float e[KBASE];
            float m = -1e30f;
            #pragma unroll
            for (int k = 0; k < KBASE; k++) { e[k] = lrow[k*6]; m = fmaxf(m, e[k]); }
            float s = 0.0f;
            #pragma unroll
            for (int k = 0; k < KBASE; k++) { e[k] = __expf(e[k] - m); s += e[k]; }
            float inv = 1.0f / s;
            ull* gm = g_mix2 + (size_t)(row0 + r)*96 + h;
            #pragma unroll
            for (int k = 0; k < KBASE; k++)
                gm[k*6] = dup2(e[k] * inv);
        }
    }
}

// ---------------------------------------------------------------------------
// Kernel 2: per (mt, b) CTA, ALL 6 heads:
//   Phase A: As[h][n][m] = sum_k mix[b,n,k,h] * wb[k,n,m]     (m-contiguous)
//   Phase B: out[b,m,h*64+c] = sum_n As[h][n][m] * x[b,n,h*64+c]
// 192 threads = 6 warps; warp = head; thread = 2 channels; 14 m-pairs in regs.
// x double-buffered via cp.async.
// ---------------------------------------------------------------------------
#define MT   28
#define NMT  7
#define CHN  28
#define NCHK 7
#define K2_SMEM ((NH*NTOK*MT + 2*CHN*DIMC) * 4)

__global__ void __launch_bounds__(192, 1) k2_mix(
    const float* __restrict__ x,
    const float* __restrict__ wb,
    float* __restrict__ out)
{
    extern __shared__ float sm2[];
    float* As = sm2;                    // [6][196][28]
    float* Xs = sm2 + NH*NTOK*MT;       // [2][28][384]

    const int tid = threadIdx.x;
    const int mt  = blockIdx.x;
    const int b   = blockIdx.y;

    const float* xsrc = x + (size_t)b*NTOK*DIMC;

    // ---- prologue: prefetch x chunks 0 and 1
    #pragma unroll
    for (int c = 0; c < 2; c++) {
        float* dst = Xs + c*(CHN*DIMC);
        const float* src = xsrc + c*(CHN*DIMC);
        for (int f = tid; f < CHN*96; f += 192)
            cp16(dst + f*4, src + f*4);
        cp_commit();
    }

    // ---------------- Phase A ----------------
    if (tid < 189) {
        const int m4 = tid % 7;
        const int nl = tid / 7;            // 0..26
        const int m0 = mt*MT + m4*4;
        for (int n = nl; n < NTOK; n += 27) {
            ull a[NH][2];
            #pragma unroll
            for (int h = 0; h < NH; h++) { a[h][0] = 0ULL; a[h][1] = 0ULL; }
            const ulonglong2* gm2 = (const ulonglong2*)(g_mix2 + (size_t)(b*NTOK + n)*96);
            const float*      wrow = wb + (size_t)n*NTOK + m0;
            #pragma unroll 4
            for (int k = 0; k < KBASE; k++) {
                ulonglong2 wv = *(const ulonglong2*)(wrow + (size_t)k*(NTOK*NTOK));
                ulonglong2 d01 = gm2[k*3+0];
                ulonglong2 d23 = gm2[k*3+1];
                ulonglong2 d45 = gm2[k*3+2];
                fma2(a[0][0], d01.x, wv.x); fma2(a[0][1], d01.x, wv.y);
                fma2(a[1][0], d01.y, wv.x); fma2(a[1][1], d01.y, wv.y);
                fma2(a[2][0], d23.x, wv.x); fma2(a[2][1], d23.x, wv.y);
                fma2(a[3][0], d23.y, wv.x); fma2(a[3][1], d23.y, wv.y);
                fma2(a[4][0], d45.x, wv.x); fma2(a[4][1], d45.x, wv.y);
                fma2(a[5][0], d45.y, wv.x); fma2(a[5][1], d45.y, wv.y);
            }
            #pragma unroll
            for (int h = 0; h < NH; h++) {
                ulonglong2 st; st.x = a[h][0]; st.y = a[h][1];
                *(ulonglong2*)(As + (h*NTOK + n)*MT + m4*4) = st;
            }
        }
    }

    // ---------------- Phase B ----------------
    const int h = tid >> 5;           // warp = head
    const int l = tid & 31;           // lane -> channels 2l, 2l+1

    ull acc[14][2];
    #pragma unroll
    for (int j = 0; j < 14; j++) { acc[j][0] = 0ULL; acc[j][1] = 0ULL; }

    for (int c = 0; c < NCHK; c++) {
        if (c < NCHK-1) asm volatile("cp.async.wait_group 1;" ::: "memory");
        else            asm volatile("cp.async.wait_group 0;" ::: "memory");
        __syncthreads();

        const float* xb = Xs + (c & 1)*(CHN*DIMC) + h*HD + 2*l;
        const ulonglong2* ap = (const ulonglong2*)(As + (h*NTOK + c*CHN)*MT);

        #pragma unroll 2
        for (int nn = 0; nn < CHN; nn++) {
            ull xp = *(const ull*)(xb + nn*DIMC);    // two adjacent channels
            float xl, xh; unpack2(xp, xl, xh);
            ull x0 = dup2(xl), x1 = dup2(xh);
            ulonglong2 q0 = ap[0], q1 = ap[1], q2 = ap[2], q3 = ap[3],
                       q4 = ap[4], q5 = ap[5], q6 = ap[6];
            ap += 7;
            fma2(acc[0][0],  q0.x, x0); fma2(acc[0][1],  q0.x, x1);
            fma2(acc[1][0],  q0.y, x0); fma2(acc[1][1],  q0.y, x1);
            fma2(acc[2][0],  q1.x, x0); fma2(acc[2][1],  q1.x, x1);
            fma2(acc[3][0],  q1.y, x0); fma2(acc[3][1],  q1.y, x1);
            fma2(acc[4][0],  q2.x, x0); fma2(acc[4][1],  q2.x, x1);
            fma2(acc[5][0],  q2.y, x0); fma2(acc[5][1],  q2.y, x1);
            fma2(acc[6][0],  q3.x, x0); fma2(acc[6][1],  q3.x, x1);
            fma2(acc[7][0],  q3.y, x0); fma2(acc[7][1],  q3.y, x1);
            fma2(acc[8][0],  q4.x, x0); fma2(acc[8][1],  q4.x, x1);
            fma2(acc[9][0],  q4.y, x0); fma2(acc[9][1],  q4.y, x1);
            fma2(acc[10][0], q5.x, x0); fma2(acc[10][1], q5.x, x1);
            fma2(acc[11][0], q5.y, x0); fma2(acc[11][1], q5.y, x1);
            fma2(acc[12][0], q6.x, x0); fma2(acc[12][1], q6.x, x1);
            fma2(acc[13][0], q6.y, x0); fma2(acc[13][1], q6.y, x1);
        }
        __syncthreads();

        if (c + 2 < NCHK) {
            float* dst = Xs + (c & 1)*(CHN*DIMC);
            const float* src = xsrc + (c+2)*(CHN*DIMC);
            for (int f = tid; f < CHN*96; f += 192)
                cp16(dst + f*4, src + f*4);
            cp_commit();
        }
    }

    // ---------------- write out ----------------
    // acc[j][q]: lanes = m-pair (2j, 2j+1), q selects channel 2l+q
    float* ob = out + ((size_t)(b*NTOK + mt*MT))*DIMC + h*HD + 2*l;
    #pragma unroll
    for (int j = 0; j < 14; j++) {
        float a0l, a0h, a1l, a1h;
        unpack2(acc[j][0], a0l, a1l);
        unpack2(acc[j][1], a0h, a1h);
        *(float2*)(ob + (size_t)(2*j)*DIMC)   = make_float2(a0l, a0h);
        *(float2*)(ob + (size_t)(2*j+1)*DIMC) = make_float2(a1l, a1h);
    }
}

// ---------------------------------------------------------------------------
extern "C" void kernel_launch(void* const* d_in, const int* in_sizes, int n_in,
                              void* d_out, int out_size)
{
    const float* x  = (const float*)d_in[0];
    const float* W1 = (const float*)d_in[1];
    const float* b1 = (const float*)d_in[2];
    const float* W2 = (const float*)d_in[3];
    const float* b2 = (const float*)d_in[4];
    const float* wb = (const float*)d_in[5];
    float* out = (float*)d_out;

    cudaFuncSetAttribute((const void*)k1_mlp,
                         cudaFuncAttributeMaxDynamicSharedMemorySize, K1_SMEM);
    cudaFuncSetAttribute((const void*)k2_mix,
                         cudaFuncAttributeMaxDynamicSharedMemorySize, K2_SMEM);

    k1_mlp<<<(BATCH*NTOK)/K1_ROWS, 192, K1_SMEM>>>(x, W1, b1, W2, b2);
    dim3 g2(NMT, BATCH);
    k2_mix<<<g2, 192, K2_SMEM>>>(x, wb, out);
}

// round 6
// speedup vs baseline: 1.8375x; 1.1971x over previous
#include <cuda_runtime.h>
#include <stdint.h>
#include <math.h>

#define BATCH 128
#define NTOK  196
#define DIMC  384
#define KBASE 16
#define NH    6
#define HD    64
#define DR    96

typedef unsigned long long ull;

// mix stored DUPLICATED: per (b,n): 16 k * 6 h * 2 copies = 192 floats = 96 ull
__device__ __align__(16) ull g_mix2[(size_t)BATCH * NTOK * 96];

__device__ __forceinline__ void fma2(ull &d, ull a, ull b) {
    asm("fma.rn.f32x2 %0, %1, %2, %0;" : "+l"(d) : "l"(a), "l"(b));
}
__device__ __forceinline__ ull dup2(float v) {
    ull r; asm("mov.b64 %0, {%1, %1};" : "=l"(r) : "f"(v)); return r;
}
__device__ __forceinline__ void unpack2(ull v, float &lo, float &hi) {
    asm("mov.b64 {%0, %1}, %2;" : "=f"(lo), "=f"(hi) : "l"(v));
}
__device__ __forceinline__ float gelu_exact(float v) {
    return 0.5f * v * (1.0f + erff(v * 0.70710678118654752440f));
}
__device__ __forceinline__ void cp16(void* dst_smem, const void* src) {
    unsigned int d = (unsigned int)__cvta_generic_to_shared(dst_smem);
    asm volatile("cp.async.cg.shared.global [%0], [%1], 16;" :: "r"(d), "l"(src));
}
__device__ __forceinline__ void cp_commit() {
    asm volatile("cp.async.commit_group;" ::: "memory");
}

// ---------------------------------------------------------------------------
// Kernel 1: mix[b,n,k,h] = softmax_k( gelu(x@W1+b1) @ W2 + b2 ), duplicated out
// CTA: 64 rows, 192 threads, 8r x 4c f32x2 tile.
// W staged in 48-row half-chunks -> smem 72KB -> 3 CTAs/SM, grid 392 = 1 wave.
// ---------------------------------------------------------------------------
#define K1_ROWS 64
#define XTP 68
#define HTP 72
#define K1_SMEM ((96*XTP + 48*96 + 96*HTP) * 4)

__global__ void __launch_bounds__(192, 3) k1_mlp(
    const float* __restrict__ x,
    const float* __restrict__ W1, const float* __restrict__ b1,
    const float* __restrict__ W2, const float* __restrict__ b2)
{
    extern __shared__ float sm1[];
    float* xs_t  = sm1;                    // [96][XTP] chunk transposed (later logits)
    float* ws    = sm1 + 96*XTP;           // [48][96]
    float* hid_t = sm1 + 96*XTP + 48*96;   // [96][HTP]
    float* lg    = xs_t;

    const int tid  = threadIdx.x;
    const int row0 = blockIdx.x * K1_ROWS;
    const int rg   = tid & 7;     // 8 row-groups of 8 rows
    const int cg   = tid >> 3;    // 24 col-groups of 4 cols

    const float4* X4  = (const float4*)x;
    const float4* W14 = (const float4*)W1;
    const float4* W24 = (const float4*)W2;

    ull acc[4][4];
    {
        float4 bv4 = *(const float4*)(b1 + cg*4);
        #pragma unroll
        for (int rp = 0; rp < 4; rp++) {
            acc[rp][0] = dup2(bv4.x); acc[rp][1] = dup2(bv4.y);
            acc[rp][2] = dup2(bv4.z); acc[rp][3] = dup2(bv4.w);
        }
    }

    // ---- GEMM1: hid = gelu(x @ W1 + b1); 4 i-chunks of 96, W in 48-halves
    for (int ci = 0; ci < 4; ci++) {
        __syncthreads();
        // stage x chunk transposed: xs_t[i][r]
        for (int f = tid; f < 1536; f += 192) {
            int r = f / 24, iv = f % 24;
            float4 v = X4[(size_t)(row0 + r) * 96 + ci*24 + iv];
            xs_t[(iv*4+0)*XTP + r] = v.x;
            xs_t[(iv*4+1)*XTP + r] = v.y;
            xs_t[(iv*4+2)*XTP + r] = v.z;
            xs_t[(iv*4+3)*XTP + r] = v.w;
        }
        #pragma unroll
        for (int hf = 0; hf < 2; hf++) {
            if (hf) __syncthreads();
            for (int f = tid; f < 1152; f += 192)
                ((float4*)ws)[f] = W14[(ci*2 + hf)*1152 + f];
            __syncthreads();

            #pragma unroll 8
            for (int i2 = 0; i2 < 48; i2++) {
                int i = hf*48 + i2;
                ulonglong2 xa = *(const ulonglong2*)(xs_t + i*XTP + rg*8);
                ulonglong2 xb = *(const ulonglong2*)(xs_t + i*XTP + rg*8 + 4);
                float4 wv = *(const float4*)(ws + i2*96 + cg*4);
                ull w0 = dup2(wv.x), w1 = dup2(wv.y), w2 = dup2(wv.z), w3 = dup2(wv.w);
                fma2(acc[0][0], xa.x, w0); fma2(acc[0][1], xa.x, w1);
                fma2(acc[0][2], xa.x, w2); fma2(acc[0][3], xa.x, w3);
                fma2(acc[1][0], xa.y, w0); fma2(acc[1][1], xa.y, w1);
                fma2(acc[1][2], xa.y, w2); fma2(acc[1][3], xa.y, w3);
                fma2(acc[2][0], xb.x, w0); fma2(acc[2][1], xb.x, w1);
                fma2(acc[2][2], xb.x, w2); fma2(acc[2][3], xb.x, w3);
                fma2(acc[3][0], xb.y, w0); fma2(acc[3][1], xb.y, w1);
                fma2(acc[3][2], xb.y, w2); fma2(acc[3][3], xb.y, w3);
            }
        }
    }
    __syncthreads();

    // ---- GELU + store hid transposed: hid_t[c][r]
    #pragma unroll
    for (int cc = 0; cc < 4; cc++) {
        float2* hrow = (float2*)(hid_t + (cg*4 + cc)*HTP + rg*8);
        #pragma unroll
        for (int rp = 0; rp < 4; rp++) {
            float lo, hi; unpack2(acc[rp][cc], lo, hi);
            hrow[rp] = make_float2(gelu_exact(lo), gelu_exact(hi));
        }
    }

    // ---- GEMM2: logits = hid @ W2 + b2, W2 in 48-halves
    {
        float4 bv4 = *(const float4*)(b2 + cg*4);
        #pragma unroll
        for (int rp = 0; rp < 4; rp++) {
            acc[rp][0] = dup2(bv4.x); acc[rp][1] = dup2(bv4.y);
            acc[rp][2] = dup2(bv4.z); acc[rp][3] = dup2(bv4.w);
        }
    }
    #pragma unroll
    for (int hf = 0; hf < 2; hf++) {
        __syncthreads();
        for (int f = tid; f < 1152; f += 192)
            ((float4*)ws)[f] = W24[hf*1152 + f];
        __syncthreads();
        #pragma unroll 8
        for (int i2 = 0; i2 < 48; i2++) {
            int i = hf*48 + i2;
            ulonglong2 xa = *(const ulonglong2*)(hid_t + i*HTP + rg*8);
            ulonglong2 xb = *(const ulonglong2*)(hid_t + i*HTP + rg*8 + 4);
            float4 wv = *(const float4*)(ws + i2*96 + cg*4);
            ull w0 = dup2(wv.x), w1 = dup2(wv.y), w2 = dup2(wv.z), w3 = dup2(wv.w);
            fma2(acc[0][0], xa.x, w0); fma2(acc[0][1], xa.x, w1);
            fma2(acc[0][2], xa.x, w2); fma2(acc[0][3], xa.x, w3);
            fma2(acc[1][0], xa.y, w0); fma2(acc[1][1], xa.y, w1);
            fma2(acc[1][2], xa.y, w2); fma2(acc[1][3], xa.y, w3);
            fma2(acc[2][0], xb.x, w0); fma2(acc[2][1], xb.x, w1);
            fma2(acc[2][2], xb.x, w2); fma2(acc[2][3], xb.x, w3);
            fma2(acc[3][0], xb.y, w0); fma2(acc[3][1], xb.y, w1);
            fma2(acc[3][2], xb.y, w2); fma2(acc[3][3], xb.y, w3);
        }
    }
    __syncthreads();
    // store logits [r][96]
    #pragma unroll
    for (int cc = 0; cc < 4; cc++) {
        #pragma unroll
        for (int rp = 0; rp < 4; rp++) {
            float lo, hi; unpack2(acc[rp][cc], lo, hi);
            lg[(rg*8 + 2*rp)*96   + cg*4 + cc] = lo;
            lg[(rg*8 + 2*rp+1)*96 + cg*4 + cc] = hi;
        }
    }
    __syncthreads();

    // ---- softmax over k per (row, h); write duplicated mix
    {
        const int h  = tid % NH;
        const int rp = tid / NH;   // 0..31
        #pragma unroll
        for (int q = 0; q < 2; q++) {
            int r = 2*rp + q;
            const float* lrow = lg + r*96 + h;
            float e[KBASE];
            float m = -1e30f;
            #pragma unroll
            for (int k = 0; k < KBASE; k++) { e[k] = lrow[k*6]; m = fmaxf(m, e[k]); }
            float s = 0.0f;
            #pragma unroll
            for (int k = 0; k < KBASE; k++) { e[k] = __expf(e[k] - m); s += e[k]; }
            float inv = 1.0f / s;
            ull* gm = g_mix2 + (size_t)(row0 + r)*96 + h;
            #pragma unroll
            for (int k = 0; k < KBASE; k++)
                gm[k*6] = dup2(e[k] * inv);
        }
    }
}

// ---------------------------------------------------------------------------
// Kernel 2: per (mt, b) CTA, all 6 heads, 384 threads (12 warps):
//   Phase A: As[h][n][m] = sum_k mix[b,n,k,h] * wb[k,n,m]
//   Phase B: warps 0-5 -> m-pairs 0-6 of head w, warps 6-11 -> m-pairs 7-13.
//            thread = 2 channels. x double-buffered via cp.async.
// ---------------------------------------------------------------------------
#define MT   28
#define NMT  7
#define CHN  28
#define NCHK 7
#define K2_SMEM ((NH*NTOK*MT + 2*CHN*DIMC) * 4)

__global__ void __launch_bounds__(384, 1) k2_mix(
    const float* __restrict__ x,
    const float* __restrict__ wb,
    float* __restrict__ out)
{
    extern __shared__ float sm2[];
    float* As = sm2;                    // [6][196][28]
    float* Xs = sm2 + NH*NTOK*MT;       // [2][28][384]

    const int tid = threadIdx.x;
    const int mt  = blockIdx.x;
    const int b   = blockIdx.y;

    const float* xsrc = x + (size_t)b*NTOK*DIMC;

    // ---- prologue: prefetch x chunks 0 and 1
    #pragma unroll
    for (int c = 0; c < 2; c++) {
        float* dst = Xs + c*(CHN*DIMC);
        const float* src = xsrc + c*(CHN*DIMC);
        for (int f = tid; f < CHN*96; f += 384)
            cp16(dst + f*4, src + f*4);
        cp_commit();
    }

    // ---------------- Phase A ----------------
    if (tid < 378) {
        const int m4 = tid % 7;
        const int nl = tid / 7;            // 0..53
        const int m0 = mt*MT + m4*4;
        for (int n = nl; n < NTOK; n += 54) {
            ull a[NH][2];
            #pragma unroll
            for (int h = 0; h < NH; h++) { a[h][0] = 0ULL; a[h][1] = 0ULL; }
            const ulonglong2* gm2 = (const ulonglong2*)(g_mix2 + (size_t)(b*NTOK + n)*96);
            const float*      wrow = wb + (size_t)n*NTOK + m0;
            #pragma unroll 4
            for (int k = 0; k < KBASE; k++) {
                ulonglong2 wv = *(const ulonglong2*)(wrow + (size_t)k*(NTOK*NTOK));
                ulonglong2 d01 = gm2[k*3+0];
                ulonglong2 d23 = gm2[k*3+1];
                ulonglong2 d45 = gm2[k*3+2];
                fma2(a[0][0], d01.x, wv.x); fma2(a[0][1], d01.x, wv.y);
                fma2(a[1][0], d01.y, wv.x); fma2(a[1][1], d01.y, wv.y);
                fma2(a[2][0], d23.x, wv.x); fma2(a[2][1], d23.x, wv.y);
                fma2(a[3][0], d23.y, wv.x); fma2(a[3][1], d23.y, wv.y);
                fma2(a[4][0], d45.x, wv.x); fma2(a[4][1], d45.x, wv.y);
                fma2(a[5][0], d45.y, wv.x); fma2(a[5][1], d45.y, wv.y);
            }
            #pragma unroll
            for (int h = 0; h < NH; h++) {
                ulonglong2 st; st.x = a[h][0]; st.y = a[h][1];
                *(ulonglong2*)(As + (h*NTOK + n)*MT + m4*4) = st;
            }
        }
    }

    // ---------------- Phase B ----------------
    const int w     = tid >> 5;
    const int l     = tid & 31;       // lane -> channels 2l, 2l+1
    const int h     = w % NH;
    const int mhalf = w / NH;         // 0: m-pairs 0-6, 1: m-pairs 7-13

    ull acc[7][2];
    #pragma unroll
    for (int j = 0; j < 7; j++) { acc[j][0] = 0ULL; acc[j][1] = 0ULL; }

    for (int c = 0; c < NCHK; c++) {
        if (c < NCHK-1) asm volatile("cp.async.wait_group 1;" ::: "memory");
        else            asm volatile("cp.async.wait_group 0;" ::: "memory");
        __syncthreads();

        const float* xb = Xs + (c & 1)*(CHN*DIMC) + h*HD + 2*l;
        const float* ab = As + (h*NTOK + c*CHN)*MT;

        if (mhalf == 0) {
            #pragma unroll 2
            for (int nn = 0; nn < CHN; nn++) {
                const float* ar = ab + nn*MT;
                ull xp = *(const ull*)(xb + nn*DIMC);
                float xl, xh; unpack2(xp, xl, xh);
                ull x0 = dup2(xl), x1 = dup2(xh);
                ulonglong2 qa = *(const ulonglong2*)(ar);       // ull 0,1
                ulonglong2 qb = *(const ulonglong2*)(ar + 4);   // ull 2,3
                ulonglong2 qc = *(const ulonglong2*)(ar + 8);   // ull 4,5
                ull        qs = *(const ull*)(ar + 12);         // ull 6
                fma2(acc[0][0], qa.x, x0); fma2(acc[0][1], qa.x, x1);
                fma2(acc[1][0], qa.y, x0); fma2(acc[1][1], qa.y, x1);
                fma2(acc[2][0], qb.x, x0); fma2(acc[2][1], qb.x, x1);
                fma2(acc[3][0], qb.y, x0); fma2(acc[3][1], qb.y, x1);
                fma2(acc[4][0], qc.x, x0); fma2(acc[4][1], qc.x, x1);
                fma2(acc[5][0], qc.y, x0); fma2(acc[5][1], qc.y, x1);
                fma2(acc[6][0], qs,   x0); fma2(acc[6][1], qs,   x1);
            }
        } else {
            #pragma unroll 2
            for (int nn = 0; nn < CHN; nn++) {
                const float* ar = ab + nn*MT;
                ull xp = *(const ull*)(xb + nn*DIMC);
                float xl, xh; unpack2(xp, xl, xh);
                ull x0 = dup2(xl), x1 = dup2(xh);
                ull        qs = *(const ull*)(ar + 14);          // ull 7
                ulonglong2 qa = *(const ulonglong2*)(ar + 16);   // ull 8,9
                ulonglong2 qb = *(const ulonglong2*)(ar + 20);   // ull 10,11
                ulonglong2 qc = *(const ulonglong2*)(ar + 24);   // ull 12,13
                fma2(acc[0][0], qs,   x0); fma2(acc[0][1], qs,   x1);
                fma2(acc[1][0], qa.x, x0); fma2(acc[1][1], qa.x, x1);
                fma2(acc[2][0], qa.y, x0); fma2(acc[2][1], qa.y, x1);
                fma2(acc[3][0], qb.x, x0); fma2(acc[3][1], qb.x, x1);
                fma2(acc[4][0], qb.y, x0); fma2(acc[4][1], qb.y, x1);
                fma2(acc[5][0], qc.x, x0); fma2(acc[5][1], qc.x, x1);
                fma2(acc[6][0], qc.y, x0); fma2(acc[6][1], qc.y, x1);
            }
        }
        __syncthreads();

        if (c + 2 < NCHK) {
            float* dst = Xs + (c & 1)*(CHN*DIMC);
            const float* src = xsrc + (c+2)*(CHN*DIMC);
            for (int f = tid; f < CHN*96; f += 384)
                cp16(dst + f*4, src + f*4);
            cp_commit();
        }
    }

    // ---------------- write out ----------------
    // acc[j][q]: lanes = m-pair (even m, odd m), q = channel 2l+q
    float* ob = out + ((size_t)(b*NTOK + mt*MT + mhalf*14))*DIMC + h*HD + 2*l;
    #pragma unroll
    for (int j = 0; j < 7; j++) {
        float a0l, a0h, a1l, a1h;
        unpack2(acc[j][0], a0l, a1l);
        unpack2(acc[j][1], a0h, a1h);
        *(float2*)(ob + (size_t)(2*j)*DIMC)   = make_float2(a0l, a0h);
        *(float2*)(ob + (size_t)(2*j+1)*DIMC) = make_float2(a1l, a1h);
    }
}

// ---------------------------------------------------------------------------
extern "C" void kernel_launch(void* const* d_in, const int* in_sizes, int n_in,
                              void* d_out, int out_size)
{
    const float* x  = (const float*)d_in[0];
    const float* W1 = (const float*)d_in[1];
    const float* b1 = (const float*)d_in[2];
    const float* W2 = (const float*)d_in[3];
    const float* b2 = (const float*)d_in[4];
    const float* wb = (const float*)d_in[5];
    float* out = (float*)d_out;

    cudaFuncSetAttribute((const void*)k1_mlp,
                         cudaFuncAttributeMaxDynamicSharedMemorySize, K1_SMEM);
    cudaFuncSetAttribute((const void*)k2_mix,
                         cudaFuncAttributeMaxDynamicSharedMemorySize, K2_SMEM);

    k1_mlp<<<(BATCH*NTOK)/K1_ROWS, 192, K1_SMEM>>>(x, W1, b1, W2, b2);
    dim3 g2(NMT, BATCH);
    k2_mix<<<g2, 384, K2_SMEM>>>(x, wb, out);
}

// round 7
// speedup vs baseline: 1.8606x; 1.0126x over previous
#include <cuda_runtime.h>
#include <stdint.h>
#include <math.h>

#define BATCH 128
#define NTOK  196
#define DIMC  384
#define KBASE 16
#define NH    6
#define HD    64
#define DR    96

typedef unsigned long long ull;

// mix stored DUPLICATED: per (b,n): 16 k * 6 h * 2 copies = 192 floats = 96 ull
__device__ __align__(16) ull g_mix2[(size_t)BATCH * NTOK * 96];

__device__ __forceinline__ void fma2(ull &d, ull a, ull b) {
    asm("fma.rn.f32x2 %0, %1, %2, %0;" : "+l"(d) : "l"(a), "l"(b));
}
__device__ __forceinline__ ull add2(ull a, ull b) {
    ull r; asm("add.rn.f32x2 %0, %1, %2;" : "=l"(r) : "l"(a), "l"(b)); return r;
}
__device__ __forceinline__ ull dup2(float v) {
    ull r; asm("mov.b64 %0, {%1, %1};" : "=l"(r) : "f"(v)); return r;
}
__device__ __forceinline__ void unpack2(ull v, float &lo, float &hi) {
    asm("mov.b64 {%0, %1}, %2;" : "=f"(lo), "=f"(hi) : "l"(v));
}
__device__ __forceinline__ float gelu_exact(float v) {
    return 0.5f * v * (1.0f + erff(v * 0.70710678118654752440f));
}
__device__ __forceinline__ void cp16(void* dst_smem, const void* src) {
    unsigned int d = (unsigned int)__cvta_generic_to_shared(dst_smem);
    asm volatile("cp.async.cg.shared.global [%0], [%1], 16;" :: "r"(d), "l"(src));
}
__device__ __forceinline__ void cp_commit() {
    asm volatile("cp.async.commit_group;" ::: "memory");
}

// ---------------------------------------------------------------------------
// Kernel 1: mix[b,n,k,h] = softmax_k( gelu(x@W1+b1) @ W2 + b2 ), duplicated out
// 64 rows, 192 threads, 8r x 4c f32x2 tile. x staged in 48-i chunks (transposed),
// W in 24-row quarters -> smem 50KB -> 4 CTAs/SM -> all 392 CTAs resident.
// ---------------------------------------------------------------------------
#define K1_ROWS 64
#define XTP 68
#define HTP 72
// xs_t [48][XTP]=3264f, ws [24][96]=2304f, hid_t [96][HTP]=6912f
#define K1_SMEM ((48*XTP + 24*96 + 96*HTP) * 4)

__global__ void __launch_bounds__(192, 4) k1_mlp(
    const float* __restrict__ x,
    const float* __restrict__ W1, const float* __restrict__ b1,
    const float* __restrict__ W2, const float* __restrict__ b2)
{
    extern __shared__ float sm1[];
    float* xs_t  = sm1;                    // [48][XTP]
    float* ws    = sm1 + 48*XTP;           // [24][96]
    float* hid_t = sm1 + 48*XTP + 24*96;   // [96][HTP]
    float* lg    = sm1;                    // [64][96] overlay (after GEMM2)

    const int tid  = threadIdx.x;
    const int row0 = blockIdx.x * K1_ROWS;
    const int rg   = tid & 7;     // 8 row-groups of 8 rows
    const int cg   = tid >> 3;    // 24 col-groups of 4 cols

    const float4* X4  = (const float4*)x;
    const float4* W14 = (const float4*)W1;
    const float4* W24 = (const float4*)W2;

    ull acc[4][4];
    {
        float4 bv4 = *(const float4*)(b1 + cg*4);
        #pragma unroll
        for (int rp = 0; rp < 4; rp++) {
            acc[rp][0] = dup2(bv4.x); acc[rp][1] = dup2(bv4.y);
            acc[rp][2] = dup2(bv4.z); acc[rp][3] = dup2(bv4.w);
        }
    }

    // ---- GEMM1: 8 i-chunks of 48; W1 in 24-row quarters
    for (int ci = 0; ci < 8; ci++) {
        __syncthreads();
        // stage x chunk transposed: xs_t[i_local][r], 768 float4 loads
        #pragma unroll
        for (int u = 0; u < 4; u++) {
            int f = tid + u*192;
            int r = f & 63, i4 = f >> 6;          // i4 0..11
            float4 v = X4[(size_t)(row0 + r) * 96 + ci*12 + i4];
            xs_t[(i4*4+0)*XTP + r] = v.x;
            xs_t[(i4*4+1)*XTP + r] = v.y;
            xs_t[(i4*4+2)*XTP + r] = v.z;
            xs_t[(i4*4+3)*XTP + r] = v.w;
        }
        #pragma unroll
        for (int q = 0; q < 2; q++) {
            if (q) __syncthreads();
            #pragma unroll
            for (int u = 0; u < 3; u++)
                ((float4*)ws)[tid + u*192] = W14[(ci*48 + q*24)*24 + tid + u*192];
            __syncthreads();

            #pragma unroll 8
            for (int j = 0; j < 24; j++) {
                int il = q*24 + j;
                ulonglong2 xa = *(const ulonglong2*)(xs_t + il*XTP + rg*8);
                ulonglong2 xb = *(const ulonglong2*)(xs_t + il*XTP + rg*8 + 4);
                float4 wv = *(const float4*)(ws + j*96 + cg*4);
                ull w0 = dup2(wv.x), w1 = dup2(wv.y), w2 = dup2(wv.z), w3 = dup2(wv.w);
                fma2(acc[0][0], xa.x, w0); fma2(acc[0][1], xa.x, w1);
                fma2(acc[0][2], xa.x, w2); fma2(acc[0][3], xa.x, w3);
                fma2(acc[1][0], xa.y, w0); fma2(acc[1][1], xa.y, w1);
                fma2(acc[1][2], xa.y, w2); fma2(acc[1][3], xa.y, w3);
                fma2(acc[2][0], xb.x, w0); fma2(acc[2][1], xb.x, w1);
                fma2(acc[2][2], xb.x, w2); fma2(acc[2][3], xb.x, w3);
                fma2(acc[3][0], xb.y, w0); fma2(acc[3][1], xb.y, w1);
                fma2(acc[3][2], xb.y, w2); fma2(acc[3][3], xb.y, w3);
            }
        }
    }
    __syncthreads();

    // ---- GELU + store hid transposed: hid_t[c][r]
    #pragma unroll
    for (int cc = 0; cc < 4; cc++) {
        float2* hrow = (float2*)(hid_t + (cg*4 + cc)*HTP + rg*8);
        #pragma unroll
        for (int rp = 0; rp < 4; rp++) {
            float lo, hi; unpack2(acc[rp][cc], lo, hi);
            hrow[rp] = make_float2(gelu_exact(lo), gelu_exact(hi));
        }
    }

    // ---- GEMM2: logits = hid @ W2 + b2; W2 in 24-row quarters
    {
        float4 bv4 = *(const float4*)(b2 + cg*4);
        #pragma unroll
        for (int rp = 0; rp < 4; rp++) {
            acc[rp][0] = dup2(bv4.x); acc[rp][1] = dup2(bv4.y);
            acc[rp][2] = dup2(bv4.z); acc[rp][3] = dup2(bv4.w);
        }
    }
    #pragma unroll
    for (int q = 0; q < 4; q++) {
        __syncthreads();
        #pragma unroll
        for (int u = 0; u < 3; u++)
            ((float4*)ws)[tid + u*192] = W24[q*576 + tid + u*192];
        __syncthreads();
        #pragma unroll 8
        for (int j = 0; j < 24; j++) {
            int i = q*24 + j;
            ulonglong2 xa = *(const ulonglong2*)(hid_t + i*HTP + rg*8);
            ulonglong2 xb = *(const ulonglong2*)(hid_t + i*HTP + rg*8 + 4);
            float4 wv = *(const float4*)(ws + j*96 + cg*4);
            ull w0 = dup2(wv.x), w1 = dup2(wv.y), w2 = dup2(wv.z), w3 = dup2(wv.w);
            fma2(acc[0][0], xa.x, w0); fma2(acc[0][1], xa.x, w1);
            fma2(acc[0][2], xa.x, w2); fma2(acc[0][3], xa.x, w3);
            fma2(acc[1][0], xa.y, w0); fma2(acc[1][1], xa.y, w1);
            fma2(acc[1][2], xa.y, w2); fma2(acc[1][3], xa.y, w3);
            fma2(acc[2][0], xb.x, w0); fma2(acc[2][1], xb.x, w1);
            fma2(acc[2][2], xb.x, w2); fma2(acc[2][3], xb.x, w3);
            fma2(acc[3][0], xb.y, w0); fma2(acc[3][1], xb.y, w1);
            fma2(acc[3][2], xb.y, w2); fma2(acc[3][3], xb.y, w3);
        }
    }
    __syncthreads();   // ws/hid dead; lg overlays sm1[0..6144)
    #pragma unroll
    for (int cc = 0; cc < 4; cc++) {
        #pragma unroll
        for (int rp = 0; rp < 4; rp++) {
            float lo, hi; unpack2(acc[rp][cc], lo, hi);
            lg[(rg*8 + 2*rp)*96   + cg*4 + cc] = lo;
            lg[(rg*8 + 2*rp+1)*96 + cg*4 + cc] = hi;
        }
    }
    __syncthreads();

    // ---- softmax over k per (row, h); write duplicated mix
    {
        const int h  = tid % NH;
        const int rp = tid / NH;   // 0..31
        #pragma unroll
        for (int q = 0; q < 2; q++) {
            int r = 2*rp + q;
            const float* lrow = lg + r*96 + h;
            float e[KBASE];
            float m = -1e30f;
            #pragma unroll
            for (int k = 0; k < KBASE; k++) { e[k] = lrow[k*6]; m = fmaxf(m, e[k]); }
            float s = 0.0f;
            #pragma unroll
            for (int k = 0; k < KBASE; k++) { e[k] = __expf(e[k] - m); s += e[k]; }
            float inv = 1.0f / s;
            ull* gm = g_mix2 + (size_t)(row0 + r)*96 + h;
            #pragma unroll
            for (int k = 0; k < KBASE; k++)
                gm[k*6] = dup2(e[k] * inv);
        }
    }
}

// ---------------------------------------------------------------------------
// Kernel 2: per (mt, b) CTA, 384 threads (12 warps):
//  Phase A: As[h][n][32] = sum_k mix*wb; row layout [14m | 2pad | 14m | 2pad]
//  Phase B: warp = (h, nhalf); lane = (msub, ci); thread tile 14m x 4c (28 ull)
//           n-halves reduced via smem at the end. x double-buffered cp.async.
// ---------------------------------------------------------------------------
#define MT    28
#define NMT   7
#define ASROW 32
#define CHN   14
#define NCHK  14
#define REDP  29   // padded ull stride for reduction buffer
// As = 6*196*32 f; aux = max(2*CHN*384, 6*32*REDP*2) f
#define K2_AUX ((2*CHN*DIMC) > (NH*32*REDP*2) ? (2*CHN*DIMC) : (NH*32*REDP*2))
#define K2_SMEM ((NH*NTOK*ASROW + K2_AUX) * 4)

__global__ void __launch_bounds__(384, 1) k2_mix(
    const float* __restrict__ x,
    const float* __restrict__ wb,
    float* __restrict__ out)
{
    extern __shared__ float sm2[];
    float* As = sm2;                       // [6][196][32]
    float* Xs = sm2 + NH*NTOK*ASROW;       // [2][14][384]  (reused for reduction)

    const int tid = threadIdx.x;
    const int mt  = blockIdx.x;
    const int b   = blockIdx.y;

    const float* xsrc = x + (size_t)b*NTOK*DIMC;

    // ---- prologue: prefetch x chunks 0 and 1
    #pragma unroll
    for (int c = 0; c < 2; c++) {
        float* dst = Xs + c*(CHN*DIMC);
        const float* src = xsrc + c*(CHN*DIMC);
        for (int f = tid; f < CHN*96; f += 384)
            cp16(dst + f*4, src + f*4);
        cp_commit();
    }

    // ---------------- Phase A ----------------
    if (tid < 378) {
        const int m4 = tid % 7;            // group of 4 m
        const int nl = tid / 7;            // 0..53
        const int m0 = mt*MT + m4*4;
        // float offsets for the two m-pairs of this group in the [14|2|14|2] row
        const int mpA = m4*2, mpB = m4*2 + 1;
        const int offA = mpA*2 + (mpA >= 7 ? 2 : 0);
        const int offB = mpB*2 + (mpB >= 7 ? 2 : 0);
        for (int n = nl; n < NTOK; n += 54) {
            ull a[NH][2];
            #pragma unroll
            for (int h = 0; h < NH; h++) { a[h][0] = 0ULL; a[h][1] = 0ULL; }
            const ulonglong2* gm2 = (const ulonglong2*)(g_mix2 + (size_t)(b*NTOK + n)*96);
            const float*      wrow = wb + (size_t)n*NTOK + m0;
            #pragma unroll 4
            for (int k = 0; k < KBASE; k++) {
                ulonglong2 wv = *(const ulonglong2*)(wrow + (size_t)k*(NTOK*NTOK));
                ulonglong2 d01 = gm2[k*3+0];
                ulonglong2 d23 = gm2[k*3+1];
                ulonglong2 d45 = gm2[k*3+2];
                fma2(a[0][0], d01.x, wv.x); fma2(a[0][1], d01.x, wv.y);
                fma2(a[1][0], d01.y, wv.x); fma2(a[1][1], d01.y, wv.y);
                fma2(a[2][0], d23.x, wv.x); fma2(a[2][1], d23.x, wv.y);
                fma2(a[3][0], d23.y, wv.x); fma2(a[3][1], d23.y, wv.y);
                fma2(a[4][0], d45.x, wv.x); fma2(a[4][1], d45.x, wv.y);
                fma2(a[5][0], d45.y, wv.x); fma2(a[5][1], d45.y, wv.y);
            }
            #pragma unroll
            for (int h = 0; h < NH; h++) {
                float* rowp = As + (h*NTOK + n)*ASROW;
                *(ull*)(rowp + offA) = a[h][0];
                *(ull*)(rowp + offB) = a[h][1];
            }
        }
    }

    // ---------------- Phase B ----------------
    const int w     = tid >> 5;
    const int l     = tid & 31;
    const int h     = w % NH;
    const int nhalf = w / NH;         // 0 or 1: n 0-6 / 7-13 within each chunk
    const int msub  = l >> 4;         // m-half: m = msub*14 + 2j (+1)
    const int ci    = l & 15;         // channels ci*4 .. ci*4+3

    ull acc[7][4];                    // [m-pair j][channel c]
    #pragma unroll
    for (int j = 0; j < 7; j++)
        #pragma unroll
        for (int c = 0; c < 4; c++) acc[j][c] = 0ULL;

    for (int c = 0; c < NCHK; c++) {
        if (c < NCHK-1) asm volatile("cp.async.wait_group 1;" ::: "memory");
        else            asm volatile("cp.async.wait_group 0;" ::: "memory");
        __syncthreads();

        const float* xb = Xs + (c & 1)*(CHN*DIMC) + h*HD + ci*4;
        const float* ab = As + (h*NTOK + c*CHN + nhalf*7)*ASROW + msub*16;

        #pragma unroll
        for (int nn = 0; nn < 7; nn++) {
            const float* ar = ab + nn*ASROW;
            ulonglong2 q01 = *(const ulonglong2*)(ar);
            ulonglong2 q23 = *(const ulonglong2*)(ar + 4);
            ulonglong2 q45 = *(const ulonglong2*)(ar + 8);
            ull        q6  = *(const ull*)(ar + 12);
            float4 xv = *(const float4*)(xb + (nn + nhalf*7)*DIMC);
            ull x0 = dup2(xv.x), x1 = dup2(xv.y), x2 = dup2(xv.z), x3 = dup2(xv.w);
            fma2(acc[0][0], q01.x, x0); fma2(acc[0][1], q01.x, x1);
            fma2(acc[0][2], q01.x, x2); fma2(acc[0][3], q01.x, x3);
            fma2(acc[1][0], q01.y, x0); fma2(acc[1][1], q01.y, x1);
            fma2(acc[1][2], q01.y, x2); fma2(acc[1][3], q01.y, x3);
            fma2(acc[2][0], q23.x, x0); fma2(acc[2][1], q23.x, x1);
            fma2(acc[2][2], q23.x, x2); fma2(acc[2][3], q23.x, x3);
            fma2(acc[3][0], q23.y, x0); fma2(acc[3][1], q23.y, x1);
            fma2(acc[3][2], q23.y, x2); fma2(acc[3][3], q23.y, x3);
            fma2(acc[4][0], q45.x, x0); fma2(acc[4][1], q45.x, x1);
            fma2(acc[4][2], q45.x, x2); fma2(acc[4][3], q45.x, x3);
            fma2(acc[5][0], q45.y, x0); fma2(acc[5][1], q45.y, x1);
            fma2(acc[5][2], q45.y, x2); fma2(acc[5][3], q45.y, x3);
            fma2(acc[6][0], q6,   x0); fma2(acc[6][1], q6,   x1);
            fma2(acc[6][2], q6,   x2); fma2(acc[6][3], q6,   x3);
        }
        __syncthreads();

        if (c + 2 < NCHK) {
            float* dst = Xs + (c & 1)*(CHN*DIMC);
            const float* src = xsrc + (c+2)*(CHN*DIMC);
            for (int f = tid; f < CHN*96; f += 384)
                cp16(dst + f*4, src + f*4);
            cp_commit();
        }
    }

    // ---------------- reduce n-halves + write out ----------------
    __syncthreads();                  // Xs free now
    ull* red = (ull*)Xs;              // [6*32][REDP]
    if (nhalf == 1) {
        ull* rp = red + (size_t)(h*32 + l)*REDP;
        #pragma unroll
        for (int j = 0; j < 7; j++)
            #pragma unroll
            for (int c = 0; c < 4; c++) rp[j*4 + c] = acc[j][c];
    }
    __syncthreads();
    if (nhalf == 0) {
        const ull* rp = red + (size_t)(h*32 + l)*REDP;
        float* ob = out + ((size_t)(b*NTOK + mt*MT + msub*14))*DIMC + h*HD + ci*4;
        #pragma unroll
        for (int j = 0; j < 7; j++) {
            float lo0,hi0,lo1,hi1,lo2,hi2,lo3,hi3;
            unpack2(add2(acc[j][0], rp[j*4+0]), lo0, hi0);
            unpack2(add2(acc[j][1], rp[j*4+1]), lo1, hi1);
            unpack2(add2(acc[j][2], rp[j*4+2]), lo2, hi2);
            unpack2(add2(acc[j][3], rp[j*4+3]), lo3, hi3);
            *(float4*)(ob + (size_t)(2*j)*DIMC)   = make_float4(lo0, lo1, lo2, lo3);
            *(float4*)(ob + (size_t)(2*j+1)*DIMC) = make_float4(hi0, hi1, hi2, hi3);
        }
    }
}

// ---------------------------------------------------------------------------
extern "C" void kernel_launch(void* const* d_in, const int* in_sizes, int n_in,
                              void* d_out, int out_size)
{
    const float* x  = (const float*)d_in[0];
    const float* W1 = (const float*)d_in[1];
    const float* b1 = (const float*)d_in[2];
    const float* W2 = (const float*)d_in[3];
    const float* b2 = (const float*)d_in[4];
    const float* wb = (const float*)d_in[5];
    float* out = (float*)d_out;

    cudaFuncSetAttribute((const void*)k1_mlp,
                         cudaFuncAttributeMaxDynamicSharedMemorySize, K1_SMEM);
    cudaFuncSetAttribute((const void*)k2_mix,
                         cudaFuncAttributeMaxDynamicSharedMemorySize, K2_SMEM);

    k1_mlp<<<(BATCH*NTOK)/K1_ROWS, 192, K1_SMEM>>>(x, W1, b1, W2, b2);
    dim3 g2(NMT, BATCH);
    k2_mix<<<g2, 384, K2_SMEM>>>(x, wb, out);
}

// round 14
// speedup vs baseline: 1.8649x; 1.0023x over previous
#include <cuda_runtime.h>
#include <stdint.h>
#include <math.h>

#define BATCH 128
#define NTOK  196
#define DIMC  384
#define KBASE 16
#define NH    6
#define HD    64
#define DR    96

typedef unsigned long long ull;

// mix stored DUPLICATED: per (b,n): 16 k * 6 h * 2 copies = 192 floats = 96 ull
__device__ __align__(16) ull g_mix2[(size_t)BATCH * NTOK * 96];

__device__ __forceinline__ void fma2(ull &d, ull a, ull b) {
    asm("fma.rn.f32x2 %0, %1, %2, %0;" : "+l"(d) : "l"(a), "l"(b));
}
__device__ __forceinline__ ull add2(ull a, ull b) {
    ull r; asm("add.rn.f32x2 %0, %1, %2;" : "=l"(r) : "l"(a), "l"(b)); return r;
}
__device__ __forceinline__ ull dup2(float v) {
    ull r; asm("mov.b64 %0, {%1, %1};" : "=l"(r) : "f"(v)); return r;
}
__device__ __forceinline__ void unpack2(ull v, float &lo, float &hi) {
    asm("mov.b64 {%0, %1}, %2;" : "=f"(lo), "=f"(hi) : "l"(v));
}
__device__ __forceinline__ float gelu_exact(float v) {
    return 0.5f * v * (1.0f + erff(v * 0.70710678118654752440f));
}
__device__ __forceinline__ void cp16(void* dst_smem, const void* src) {
    unsigned int d = (unsigned int)__cvta_generic_to_shared(dst_smem);
    asm volatile("cp.async.cg.shared.global [%0], [%1], 16;" :: "r"(d), "l"(src));
}
__device__ __forceinline__ void cp_commit() {
    asm volatile("cp.async.commit_group;" ::: "memory");
}

// ---------------------------------------------------------------------------
// Kernel 1 (round-6 variant, best measured): 64 rows, 192 threads, 8r x 4c.
// W staged in 48-row half-chunks -> smem 72KB -> 3 CTAs/SM.
// ---------------------------------------------------------------------------
#define K1_ROWS 64
#define XTP 68
#define HTP 72
#define K1_SMEM ((96*XTP + 48*96 + 96*HTP) * 4)

__global__ void __launch_bounds__(192, 3) k1_mlp(
    const float* __restrict__ x,
    const float* __restrict__ W1, const float* __restrict__ b1,
    const float* __restrict__ W2, const float* __restrict__ b2)
{
    extern __shared__ float sm1[];
    float* xs_t  = sm1;                    // [96][XTP] chunk transposed (later logits)
    float* ws    = sm1 + 96*XTP;           // [48][96]
    float* hid_t = sm1 + 96*XTP + 48*96;   // [96][HTP]
    float* lg    = xs_t;

    const int tid  = threadIdx.x;
    const int row0 = blockIdx.x * K1_ROWS;
    const int rg   = tid & 7;     // 8 row-groups of 8 rows
    const int cg   = tid >> 3;    // 24 col-groups of 4 cols

    const float4* X4  = (const float4*)x;
    const float4* W14 = (const float4*)W1;
    const float4* W24 = (const float4*)W2;

    ull acc[4][4];
    {
        float4 bv4 = *(const float4*)(b1 + cg*4);
        #pragma unroll
        for (int rp = 0; rp < 4; rp++) {
            acc[rp][0] = dup2(bv4.x); acc[rp][1] = dup2(bv4.y);
            acc[rp][2] = dup2(bv4.z); acc[rp][3] = dup2(bv4.w);
        }
    }

    // ---- GEMM1: hid = gelu(x @ W1 + b1); 4 i-chunks of 96, W in 48-halves
    for (int ci = 0; ci < 4; ci++) {
        __syncthreads();
        for (int f = tid; f < 1536; f += 192) {
            int r = f / 24, iv = f % 24;
            float4 v = X4[(size_t)(row0 + r) * 96 + ci*24 + iv];
            xs_t[(iv*4+0)*XTP + r] = v.x;
            xs_t[(iv*4+1)*XTP + r] = v.y;
            xs_t[(iv*4+2)*XTP + r] = v.z;
            xs_t[(iv*4+3)*XTP + r] = v.w;
        }
        #pragma unroll
        for (int hf = 0; hf < 2; hf++) {
            if (hf) __syncthreads();
            for (int f = tid; f < 1152; f += 192)
                ((float4*)ws)[f] = W14[(ci*2 + hf)*1152 + f];
            __syncthreads();

            #pragma unroll 8
            for (int i2 = 0; i2 < 48; i2++) {
                int i = hf*48 + i2;
                ulonglong2 xa = *(const ulonglong2*)(xs_t + i*XTP + rg*8);
                ulonglong2 xb = *(const ulonglong2*)(xs_t + i*XTP + rg*8 + 4);
                float4 wv = *(const float4*)(ws + i2*96 + cg*4);
                ull w0 = dup2(wv.x), w1 = dup2(wv.y), w2 = dup2(wv.z), w3 = dup2(wv.w);
                fma2(acc[0][0], xa.x, w0); fma2(acc[0][1], xa.x, w1);
                fma2(acc[0][2], xa.x, w2); fma2(acc[0][3], xa.x, w3);
                fma2(acc[1][0], xa.y, w0); fma2(acc[1][1], xa.y, w1);
                fma2(acc[1][2], xa.y, w2); fma2(acc[1][3], xa.y, w3);
                fma2(acc[2][0], xb.x, w0); fma2(acc[2][1], xb.x, w1);
                fma2(acc[2][2], xb.x, w2); fma2(acc[2][3], xb.x, w3);
                fma2(acc[3][0], xb.y, w0); fma2(acc[3][1], xb.y, w1);
                fma2(acc[3][2], xb.y, w2); fma2(acc[3][3], xb.y, w3);
            }
        }
    }
    __syncthreads();

    // ---- GELU + store hid transposed: hid_t[c][r]
    #pragma unroll
    for (int cc = 0; cc < 4; cc++) {
        float2* hrow = (float2*)(hid_t + (cg*4 + cc)*HTP + rg*8);
        #pragma unroll
        for (int rp = 0; rp < 4; rp++) {
            float lo, hi; unpack2(acc[rp][cc], lo, hi);
            hrow[rp] = make_float2(gelu_exact(lo), gelu_exact(hi));
        }
    }

    // ---- GEMM2: logits = hid @ W2 + b2, W2 in 48-halves
    {
        float4 bv4 = *(const float4*)(b2 + cg*4);
        #pragma unroll
        for (int rp = 0; rp < 4; rp++) {
            acc[rp][0] = dup2(bv4.x); acc[rp][1] = dup2(bv4.y);
            acc[rp][2] = dup2(bv4.z); acc[rp][3] = dup2(bv4.w);
        }
    }
    #pragma unroll
    for (int hf = 0; hf < 2; hf++) {
        __syncthreads();
        for (int f = tid; f < 1152; f += 192)
            ((float4*)ws)[f] = W24[hf*1152 + f];
        __syncthreads();
        #pragma unroll 8
        for (int i2 = 0; i2 < 48; i2++) {
            int i = hf*48 + i2;
            ulonglong2 xa = *(const ulonglong2*)(hid_t + i*HTP + rg*8);
            ulonglong2 xb = *(const ulonglong2*)(hid_t + i*HTP + rg*8 + 4);
            float4 wv = *(const float4*)(ws + i2*96 + cg*4);
            ull w0 = dup2(wv.x), w1 = dup2(wv.y), w2 = dup2(wv.z), w3 = dup2(wv.w);
            fma2(acc[0][0], xa.x, w0); fma2(acc[0][1], xa.x, w1);
            fma2(acc[0][2], xa.x, w2); fma2(acc[0][3], xa.x, w3);
            fma2(acc[1][0], xa.y, w0); fma2(acc[1][1], xa.y, w1);
            fma2(acc[1][2], xa.y, w2); fma2(acc[1][3], xa.y, w3);
            fma2(acc[2][0], xb.x, w0); fma2(acc[2][1], xb.x, w1);
            fma2(acc[2][2], xb.x, w2); fma2(acc[2][3], xb.x, w3);
            fma2(acc[3][0], xb.y, w0); fma2(acc[3][1], xb.y, w1);
            fma2(acc[3][2], xb.y, w2); fma2(acc[3][3], xb.y, w3);
        }
    }
    __syncthreads();
    #pragma unroll
    for (int cc = 0; cc < 4; cc++) {
        #pragma unroll
        for (int rp = 0; rp < 4; rp++) {
            float lo, hi; unpack2(acc[rp][cc], lo, hi);
            lg[(rg*8 + 2*rp)*96   + cg*4 + cc] = lo;
            lg[(rg*8 + 2*rp+1)*96 + cg*4 + cc] = hi;
        }
    }
    __syncthreads();

    // ---- softmax over k per (row, h); write duplicated mix
    {
        const int h  = tid % NH;
        const int rp = tid / NH;   // 0..31
        #pragma unroll
        for (int q = 0; q < 2; q++) {
            int r = 2*rp + q;
            const float* lrow = lg + r*96 + h;
            float e[KBASE];
            float m = -1e30f;
            #pragma unroll
            for (int k = 0; k < KBASE; k++) { e[k] = lrow[k*6]; m = fmaxf(m, e[k]); }
            float s = 0.0f;
            #pragma unroll
            for (int k = 0; k < KBASE; k++) { e[k] = __expf(e[k] - m); s += e[k]; }
            float inv = 1.0f / s;
            ull* gm = g_mix2 + (size_t)(row0 + r)*96 + h;
            #pragma unroll
            for (int k = 0; k < KBASE; k++)
                gm[k*6] = dup2(e[k] * inv);
        }
    }
}

// ---------------------------------------------------------------------------
// Kernel 2: per (mt, b) CTA, 384 threads (12 warps):
//  Phase A: As[h][n][32] = sum_k mix*wb; row layout [14m | 2pad | 14m | 2pad]
//  Phase B: warp = (h, nhalf); lane = (msub, ci); thread tile 14m x 4c.
//  Inner loop SOFTWARE-PIPELINED: A/x for n+1 loaded before n's FMA block.
// ---------------------------------------------------------------------------
#define MT    28
#define NMT   7
#define ASROW 32
#define CHN   14
#define NCHK  14
#define REDP  29
#define K2_AUX ((2*CHN*DIMC) > (NH*32*REDP*2) ? (2*CHN*DIMC) : (NH*32*REDP*2))
#define K2_SMEM ((NH*NTOK*ASROW + K2_AUX) * 4)

__global__ void __launch_bounds__(384, 1) k2_mix(
    const float* __restrict__ x,
    const float* __restrict__ wb,
    float* __restrict__ out)
{
    extern __shared__ float sm2[];
    float* As = sm2;                       // [6][196][32]
    float* Xs = sm2 + NH*NTOK*ASROW;       // [2][14][384]  (reused for reduction)

    const int tid = threadIdx.x;
    const int mt  = blockIdx.x;
    const int b   = blockIdx.y;

    const float* xsrc = x + (size_t)b*NTOK*DIMC;

    // ---- prologue: prefetch x chunks 0 and 1
    #pragma unroll
    for (int c = 0; c < 2; c++) {
        float* dst = Xs + c*(CHN*DIMC);
        const float* src = xsrc + c*(CHN*DIMC);
        for (int f = tid; f < CHN*96; f += 384)
            cp16(dst + f*4, src + f*4);
        cp_commit();
    }

    // ---------------- Phase A ----------------
    if (tid < 378) {
        const int m4 = tid % 7;
        const int nl = tid / 7;            // 0..53
        const int m0 = mt*MT + m4*4;
        const int mpA = m4*2, mpB = m4*2 + 1;
        const int offA = mpA*2 + (mpA >= 7 ? 2 : 0);
        const int offB = mpB*2 + (mpB >= 7 ? 2 : 0);
        for (int n = nl; n < NTOK; n += 54) {
            ull a[NH][2];
            #pragma unroll
            for (int h = 0; h < NH; h++) { a[h][0] = 0ULL; a[h][1] = 0ULL; }
            const ulonglong2* gm2 = (const ulonglong2*)(g_mix2 + (size_t)(b*NTOK + n)*96);
            const float*      wrow = wb + (size_t)n*NTOK + m0;
            #pragma unroll 4
            for (int k = 0; k < KBASE; k++) {
                ulonglong2 wv = *(const ulonglong2*)(wrow + (size_t)k*(NTOK*NTOK));
                ulonglong2 d01 = gm2[k*3+0];
                ulonglong2 d23 = gm2[k*3+1];
                ulonglong2 d45 = gm2[k*3+2];
                fma2(a[0][0], d01.x, wv.x); fma2(a[0][1], d01.x, wv.y);
                fma2(a[1][0], d01.y, wv.x); fma2(a[1][1], d01.y, wv.y);
                fma2(a[2][0], d23.x, wv.x); fma2(a[2][1], d23.x, wv.y);
                fma2(a[3][0], d23.y, wv.x); fma2(a[3][1], d23.y, wv.y);
                fma2(a[4][0], d45.x, wv.x); fma2(a[4][1], d45.x, wv.y);
                fma2(a[5][0], d45.y, wv.x); fma2(a[5][1], d45.y, wv.y);
            }
            #pragma unroll
            for (int h = 0; h < NH; h++) {
                float* rowp = As + (h*NTOK + n)*ASROW;
                *(ull*)(rowp + offA) = a[h][0];
                *(ull*)(rowp + offB) = a[h][1];
            }
        }
    }

    // ---------------- Phase B ----------------
    const int w     = tid >> 5;
    const int l     = tid & 31;
    const int h     = w % NH;
    const int nhalf = w / NH;         // 0 or 1: n 0-6 / 7-13 within each chunk
    const int msub  = l >> 4;
    const int ci    = l & 15;

    ull acc[7][4];
    #pragma unroll
    for (int j = 0; j < 7; j++)
        #pragma unroll
        for (int c = 0; c < 4; c++) acc[j][c] = 0ULL;

    for (int c = 0; c < NCHK; c++) {
        if (c < NCHK-1) asm volatile("cp.async.wait_group 1;" ::: "memory");
        else            asm volatile("cp.async.wait_group 0;" ::: "memory");
        __syncthreads();

        const float* xb = Xs + (c & 1)*(CHN*DIMC) + h*HD + ci*4 + nhalf*7*DIMC;
        const float* ab = As + (h*NTOK + c*CHN + nhalf*7)*ASROW + msub*16;

        // software-pipelined: preload n=0, then load n+1 before n's FMAs
        ulonglong2 q01 = *(const ulonglong2*)(ab);
        ulonglong2 q23 = *(const ulonglong2*)(ab + 4);
        ulonglong2 q45 = *(const ulonglong2*)(ab + 8);
        ull        q6  = *(const ull*)(ab + 12);
        float4     xv  = *(const float4*)(xb);

        #pragma unroll
        for (int nn = 0; nn < 7; nn++) {
            ulonglong2 p01, p23, p45; ull p6; float4 pxv;
            if (nn < 6) {
                const float* ar = ab + (nn+1)*ASROW;
                p01 = *(const ulonglong2*)(ar);
                p23 = *(const ulonglong2*)(ar + 4);
                p45 = *(const ulonglong2*)(ar + 8);
                p6  = *(const ull*)(ar + 12);
                pxv = *(const float4*)(xb + (nn+1)*DIMC);
            }
            ull x0 = dup2(xv.x), x1 = dup2(xv.y), x2 = dup2(xv.z), x3 = dup2(xv.w);
            fma2(acc[0][0], q01.x, x0); fma2(acc[0][1], q01.x, x1);
            fma2(acc[0][2], q01.x, x2); fma2(acc[0][3], q01.x, x3);
            fma2(acc[1][0], q01.y, x0); fma2(acc[1][1], q01.y, x1);
            fma2(acc[1][2], q01.y, x2); fma2(acc[1][3], q01.y, x3);
            fma2(acc[2][0], q23.x, x0); fma2(acc[2][1], q23.x, x1);
            fma2(acc[2][2], q23.x, x2); fma2(acc[2][3], q23.x, x3);
            fma2(acc[3][0], q23.y, x0); fma2(acc[3][1], q23.y, x1);
            fma2(acc[3][2], q23.y, x2); fma2(acc[3][3], q23.y, x3);
            fma2(acc[4][0], q45.x, x0); fma2(acc[4][1], q45.x, x1);
            fma2(acc[4][2], q45.x, x2); fma2(acc[4][3], q45.x, x3);
            fma2(acc[5][0], q45.y, x0); fma2(acc[5][1], q45.y, x1);
            fma2(acc[5][2], q45.y, x2); fma2(acc[5][3], q45.y, x3);
            fma2(acc[6][0], q6,   x0); fma2(acc[6][1], q6,   x1);
            fma2(acc[6][2], q6,   x2); fma2(acc[6][3], q6,   x3);
            if (nn < 6) { q01 = p01; q23 = p23; q45 = p45; q6 = p6; xv = pxv; }
        }
        __syncthreads();

        if (c + 2 < NCHK) {
            float* dst = Xs + (c & 1)*(CHN*DIMC);
            const float* src = xsrc + (c+2)*(CHN*DIMC);
            for (int f = tid; f < CHN*96; f += 384)
                cp16(dst + f*4, src + f*4);
            cp_commit();
        }
    }

    // ---------------- reduce n-halves + write out ----------------
    __syncthreads();
    ull* red = (ull*)Xs;
    if (nhalf == 1) {
        ull* rp = red + (size_t)(h*32 + l)*REDP;
        #pragma unroll
        for (int j = 0; j < 7; j++)
            #pragma unroll
            for (int c = 0; c < 4; c++) rp[j*4 + c] = acc[j][c];
    }
    __syncthreads();
    if (nhalf == 0) {
        const ull* rp = red + (size_t)(h*32 + l)*REDP;
        float* ob = out + ((size_t)(b*NTOK + mt*MT + msub*14))*DIMC + h*HD + ci*4;
        #pragma unroll
        for (int j = 0; j < 7; j++) {
            float lo0,hi0,lo1,hi1,lo2,hi2,lo3,hi3;
            unpack2(add2(acc[j][0], rp[j*4+0]), lo0, hi0);
            unpack2(add2(acc[j][1], rp[j*4+1]), lo1, hi1);
            unpack2(add2(acc[j][2], rp[j*4+2]), lo2, hi2);
            unpack2(add2(acc[j][3], rp[j*4+3]), lo3, hi3);
            *(float4*)(ob + (size_t)(2*j)*DIMC)   = make_float4(lo0, lo1, lo2, lo3);
            *(float4*)(ob + (size_t)(2*j+1)*DIMC) = make_float4(hi0, hi1, hi2, hi3);
        }
    }
}

// ---------------------------------------------------------------------------
extern "C" void kernel_launch(void* const* d_in, const int* in_sizes, int n_in,
                              void* d_out, int out_size)
{
    const float* x  = (const float*)d_in[0];
    const float* W1 = (const float*)d_in[1];
    const float* b1 = (const float*)d_in[2];
    const float* W2 = (const float*)d_in[3];
    const float* b2 = (const float*)d_in[4];
    const float* wb = (const float*)d_in[5];
    float* out = (float*)d_out;

    cudaFuncSetAttribute((const void*)k1_mlp,
                         cudaFuncAttributeMaxDynamicSharedMemorySize, K1_SMEM);
    cudaFuncSetAttribute((const void*)k2_mix,
                         cudaFuncAttributeMaxDynamicSharedMemorySize, K2_SMEM);

    k1_mlp<<<(BATCH*NTOK)/K1_ROWS, 192, K1_SMEM>>>(x, W1, b1, W2, b2);
    dim3 g2(NMT, BATCH);
    k2_mix<<<g2, 384, K2_SMEM>>>(x, wb, out);
}